// round 7
// baseline (speedup 1.0000x reference)
#include <cuda_runtime.h>
#include <cstdint>

#define BETA_C (8.0f / 3.0f)

// ---------------- scalar step (tail kernel only) ----------------
__device__ __forceinline__ void lorenz_step(float yin0, float yin1, float yin2,
                                            float& o0, float& o1, float& o2) {
    const float h  = 0.01f;
    const float c1 = 0.5f * h;
    const float c2 = h * h / 6.0f;
    const float c3 = h * h * h / 8.0f;
    const float c4 = h * h * h / 24.0f;

    float y0 = 10.0f * yin0, y1 = 10.0f * yin1, y2 = 10.0f * yin2;
    float f0 = 10.0f * y1 - 10.0f * y0;
    float f1 = 28.0f * y0 - y0 * y2 - y1;
    float f2 = y0 * y1 - BETA_C * y2;
    float j00 = 28.0f - y2;
    float dff0 = 10.0f * f1 - 10.0f * f0;
    float dff1 = j00 * f0 - f1 - y0 * f2;
    float dff2 = y1 * f0 + y0 * f1 - BETA_C * f2;
    float dfdff0 = 10.0f * dff1 - 10.0f * dff0;
    float dfdff1 = j00 * dff0 - dff1 - y0 * dff2;
    float dfdff2 = y1 * dff0 + y0 * dff1 - BETA_C * dff2;
    float ddfff1 = -2.0f * f0 * f2;
    float ddfff2 =  2.0f * f0 * f1;
    float ddfdfff1 = -dff0 * f2 - dff2 * f0;
    float ddfdfff2 =  dff0 * f1 + dff1 * f0;
    float dfddfff0 = 10.0f * ddfff1;
    float dfddfff1 = -ddfff1 - y0 * ddfff2;
    float dfddfff2 = y0 * f1 - BETA_C * ddfff2;
    float dfdfdff0 = 10.0f * dfdff1 - 10.0f * dfdff0;
    float dfdfdff1 = j00 * dfdff0 - dfdff1 - y0 * dfdff2;
    float dfdfdff2 = y1 * dfdff0 + y0 * dfdff1 - BETA_C * dfdff2;
    o0 = (f0 + c1 * dff0 + c2 * dfdff0 + c4 * (dfddfff0 + dfdfdff0)) * 0.1f;
    o1 = (f1 + c1 * dff1 + c2 * (ddfff1 + dfdff1)
             + c3 * ddfdfff1 + c4 * (dfddfff1 + dfdfdff1)) * 0.1f;
    o2 = (f2 + c1 * dff2 + c2 * (ddfff2 + dfdff2)
             + c3 * ddfdfff2 + c4 * (dfddfff2 + dfdfdff2)) * 0.1f;
}

// ---------------- packed f32x2 primitives ----------------
__device__ __forceinline__ uint64_t f2pk(float lo, float hi) {
    uint64_t d;
    asm("mov.b64 %0, {%1, %2};" : "=l"(d)
        : "r"(__float_as_uint(lo)), "r"(__float_as_uint(hi)));
    return d;
}
__device__ __forceinline__ void f2up(uint64_t v, float& lo, float& hi) {
    uint32_t a, b;
    asm("mov.b64 {%0, %1}, %2;" : "=r"(a), "=r"(b) : "l"(v));
    lo = __uint_as_float(a); hi = __uint_as_float(b);
}
__device__ __forceinline__ uint64_t f2mul(uint64_t a, uint64_t b) {
    uint64_t d; asm("mul.rn.f32x2 %0, %1, %2;" : "=l"(d) : "l"(a), "l"(b)); return d;
}
__device__ __forceinline__ uint64_t f2add(uint64_t a, uint64_t b) {
    uint64_t d; asm("add.rn.f32x2 %0, %1, %2;" : "=l"(d) : "l"(a), "l"(b)); return d;
}
__device__ __forceinline__ uint64_t f2fma(uint64_t a, uint64_t b, uint64_t c) {
    uint64_t d; asm("fma.rn.f32x2 %0, %1, %2, %3;" : "=l"(d) : "l"(a), "l"(b), "l"(c)); return d;
}

// Packed Lorenz Taylor step: processes TWO triples at once.
struct PkConsts {
    uint64_t K10, K28, KnB, Kn2, K2, Kn1, K01, Kc1, Kc2, Kc3, Knc3, Kc4;
};
__device__ __forceinline__ PkConsts make_consts() {
    const float h = 0.01f;
    PkConsts k;
    k.K10 = f2pk(10.0f, 10.0f);
    k.K28 = f2pk(28.0f, 28.0f);
    k.KnB = f2pk(-BETA_C, -BETA_C);
    k.Kn2 = f2pk(-2.0f, -2.0f);
    k.K2  = f2pk(2.0f, 2.0f);
    k.Kn1 = f2pk(-1.0f, -1.0f);
    k.K01 = f2pk(0.1f, 0.1f);
    k.Kc1 = f2pk(0.5f * h, 0.5f * h);
    k.Kc2 = f2pk(h * h / 6.0f, h * h / 6.0f);
    k.Kc3 = f2pk(h * h * h / 8.0f, h * h * h / 8.0f);
    k.Knc3 = f2pk(-h * h * h / 8.0f, -h * h * h / 8.0f);
    k.Kc4 = f2pk(h * h * h / 24.0f, h * h * h / 24.0f);
    return k;
}

// sub(a,b) = fma(b, -1, a)
#define F2SUB(a, b) f2fma((b), k.Kn1, (a))

__device__ __forceinline__ void lorenz2(const PkConsts& k,
                                        uint64_t& x0, uint64_t& x1, uint64_t& x2) {
    uint64_t y0 = f2mul(k.K10, x0);
    uint64_t y1 = f2mul(k.K10, x1);
    uint64_t y2 = f2mul(k.K10, x2);

    uint64_t f0 = f2mul(k.K10, F2SUB(y1, y0));
    uint64_t j  = F2SUB(k.K28, y2);                      // 28 - y2
    uint64_t f1 = F2SUB(f2mul(y0, j), y1);               // y0*(28-y2) - y1
    uint64_t f2v = f2fma(y0, y1, f2mul(k.KnB, y2));      // y0*y1 - B*y2

    // jac(v) = (10*(v1-v0), j*v0 - v1 - y0*v2, y1*v0 + y0*v1 - B*v2)
    uint64_t dff0 = f2mul(k.K10, F2SUB(f1, f0));
    uint64_t dff1 = F2SUB(f2mul(j, f0), f2fma(y0, f2v, f1));
    uint64_t dff2 = f2fma(y1, f0, f2fma(y0, f1, f2mul(k.KnB, f2v)));

    uint64_t dfdff0 = f2mul(k.K10, F2SUB(dff1, dff0));
    uint64_t dfdff1 = F2SUB(f2mul(j, dff0), f2fma(y0, dff2, dff1));
    uint64_t dfdff2 = f2fma(y1, dff0, f2fma(y0, dff1, f2mul(k.KnB, dff2)));

    uint64_t ddfff1 = f2mul(k.Kn2, f2mul(f0, f2v));      // -2*f0*f2
    uint64_t ddfff2 = f2mul(k.K2,  f2mul(f0, f1));       //  2*f0*f1

    uint64_t nddfdfff1 = f2fma(dff0, f2v, f2mul(dff2, f0));  // = -ddfdfff1
    uint64_t ddfdfff2  = f2fma(dff0, f1,  f2mul(dff1, f0));

    uint64_t dfddfff0  = f2mul(k.K10, ddfff1);
    uint64_t ndfddfff1 = f2fma(y0, ddfff2, ddfff1);          // = -dfddfff1
    uint64_t dfddfff2  = f2fma(y0, f1, f2mul(k.KnB, ddfff2)); // y0*f1 - B*ddfff2 (ref quirk)

    uint64_t dfdfdff0 = f2mul(k.K10, F2SUB(dfdff1, dfdff0));
    uint64_t dfdfdff1 = F2SUB(f2mul(j, dfdff0), f2fma(y0, dfdff2, dfdff1));
    uint64_t dfdfdff2 = f2fma(y1, dfdff0, f2fma(y0, dfdff1, f2mul(k.KnB, dfdff2)));

    // o0 = (f0 + c1*dff0 + c2*dfdff0 + c4*(dfddfff0 + dfdfdff0)) * 0.1
    uint64_t acc = f2fma(k.Kc1, dff0, f0);
    acc = f2fma(k.Kc2, dfdff0, acc);
    acc = f2fma(k.Kc4, f2add(dfddfff0, dfdfdff0), acc);
    x0 = f2mul(k.K01, acc);

    // o1 = (f1 + c1*dff1 + c2*(ddfff1+dfdff1) + c3*ddfdfff1 + c4*(dfddfff1+dfdfdff1)) * 0.1
    acc = f2fma(k.Kc1, dff1, f1);
    acc = f2fma(k.Kc2, f2add(ddfff1, dfdff1), acc);
    acc = f2fma(k.Knc3, nddfdfff1, acc);
    acc = f2fma(k.Kc4, F2SUB(dfdfdff1, ndfddfff1), acc);
    x1 = f2mul(k.K01, acc);

    // o2 = (f2 + c1*dff2 + c2*(ddfff2+dfdff2) + c3*ddfdfff2 + c4*(dfddfff2+dfdfdff2)) * 0.1
    acc = f2fma(k.Kc1, dff2, f2v);
    acc = f2fma(k.Kc2, f2add(ddfff2, dfdff2), acc);
    acc = f2fma(k.Kc3, ddfdfff2, acc);
    acc = f2fma(k.Kc4, f2add(dfddfff2, dfdfdff2), acc);
    x2 = f2mul(k.K01, acc);
}

// Warp-autonomous tiles: each warp owns 96 float4s (128 triples) of smem.
// Coalesced LDG/STG; smem does the AoS<->triple transpose; math is packed f32x2.
__global__ void IE_LS_kernel(const float4* __restrict__ in,
                             float4* __restrict__ out) {
    __shared__ float4 s[768];   // 8 warps * 96

    const int lane = threadIdx.x & 31;
    const int warp = threadIdx.x >> 5;
    float4* sw = s + warp * 96;
    const long long gbase = (long long)blockIdx.x * 768 + warp * 96;

#pragma unroll
    for (int kk = 0; kk < 3; kk++)
        sw[lane + 32 * kk] = in[gbase + lane + 32 * kk];
    __syncwarp();

    // lane owns float4s 3*lane..3*lane+2 = triples A,B,C,D
    float4 a = sw[3 * lane + 0];
    float4 b = sw[3 * lane + 1];
    float4 c = sw[3 * lane + 2];

    const PkConsts k = make_consts();

    // pair (A,B) and (C,D)
    uint64_t u0 = f2pk(a.x, a.w);
    uint64_t u1 = f2pk(a.y, b.x);
    uint64_t u2 = f2pk(a.z, b.y);
    uint64_t v0 = f2pk(b.z, c.y);
    uint64_t v1 = f2pk(b.w, c.z);
    uint64_t v2 = f2pk(c.x, c.w);

    lorenz2(k, u0, u1, u2);
    lorenz2(k, v0, v1, v2);

    f2up(u0, a.x, a.w);
    f2up(u1, a.y, b.x);
    f2up(u2, a.z, b.y);
    f2up(v0, b.z, c.y);
    f2up(v1, b.w, c.z);
    f2up(v2, c.x, c.w);

    sw[3 * lane + 0] = a;
    sw[3 * lane + 1] = b;
    sw[3 * lane + 2] = c;
    __syncwarp();

#pragma unroll
    for (int kk = 0; kk < 3; kk++)
        out[gbase + lane + 32 * kk] = sw[lane + 32 * kk];
}

// Tail kernel for leftover triples (not hit for the bench shape).
__global__ void IE_LS_tail_kernel(const float* __restrict__ in,
                                  float* __restrict__ out,
                                  int start_triple, int n_triples) {
    int t = start_triple + blockIdx.x * blockDim.x + threadIdx.x;
    if (t >= n_triples) return;
    float o0, o1, o2;
    lorenz_step(in[3 * t], in[3 * t + 1], in[3 * t + 2], o0, o1, o2);
    out[3 * t] = o0; out[3 * t + 1] = o1; out[3 * t + 2] = o2;
}

extern "C" void kernel_launch(void* const* d_in, const int* in_sizes, int n_in,
                              void* d_out, int out_size) {
    const float* in = (const float*)d_in[0];
    float* out = (float*)d_out;
    int n_elems = in_sizes[0];            // 12582912 = 4194304 * 3
    int n_triples = n_elems / 3;
    int n_blocks = n_triples / 1024;      // 1024 triples per 256-thread block

    if (n_blocks > 0) {
        IE_LS_kernel<<<n_blocks, 256>>>((const float4*)in, (float4*)out);
    }
    int done = n_blocks * 1024;
    int rem = n_triples - done;
    if (rem > 0) {
        IE_LS_tail_kernel<<<(rem + 255) / 256, 256>>>(in, out, done, n_triples);
    }
}